// round 5
// baseline (speedup 1.0000x reference)
#include <cuda_runtime.h>
#include <cstdint>

#define D      768
#define LSEQ   528
#define BSZ    64
#define NHEADS 12
#define DH     64
#define MTOT   (BSZ * LSEQ)           // 33792
#define SCALE  0.03608439182435161f   // 768^-0.5
#define WELEM  (D * D)                // 589824

// Scratch (allocation-free rule: __device__ globals). All tf32-as-uint32.
__device__ uint32_t g_xt[(size_t)MTOT * D];
__device__ uint32_t g_qt[(size_t)MTOT * D];
__device__ uint32_t g_kt[(size_t)MTOT * D];
__device__ uint32_t g_vt[(size_t)MTOT * D];
__device__ uint32_t g_att[(size_t)MTOT * D];
__device__ uint32_t g_wt[4 * (size_t)WELEM];   // Wq, Wk, Wv, Wp (tf32)

__device__ __forceinline__ uint32_t f2tf32(float f) {
    uint32_t u;
    asm("cvt.rna.tf32.f32 %0, %1;" : "=r"(u) : "f"(f));
    return u;
}

__device__ __forceinline__ void mma_tf32(float c[4], uint32_t a0, uint32_t a1,
                                         uint32_t a2, uint32_t a3,
                                         uint32_t b0, uint32_t b1) {
    asm volatile(
        "mma.sync.aligned.m16n8k8.row.col.f32.tf32.tf32.f32 "
        "{%0,%1,%2,%3}, {%4,%5,%6,%7}, {%8,%9}, {%0,%1,%2,%3};"
        : "+f"(c[0]), "+f"(c[1]), "+f"(c[2]), "+f"(c[3])
        : "r"(a0), "r"(a1), "r"(a2), "r"(a3), "r"(b0), "r"(b1));
}

__device__ __forceinline__ void cp16(uint32_t smem_dst, const void* gsrc) {
    asm volatile("cp.async.cg.shared.global [%0], [%1], 16;\n"
                 :: "r"(smem_dst), "l"(gsrc));
}
#define CP_COMMIT() asm volatile("cp.async.commit_group;\n" ::: "memory")
#define CP_WAIT(N)  asm volatile("cp.async.wait_group %0;\n" :: "n"(N) : "memory")

// ---------------------------------------------------------------------------
// Single fused fp32 -> tf32 convert: x followed by the 4 weights.
// ---------------------------------------------------------------------------
#define XN4 ((MTOT * (size_t)D) / 4)     // 6488064
#define WN4 (WELEM / 4)                  // 147456
#define TOTN4 (XN4 + 4 * (size_t)WN4)    // 7077888

__global__ void cvt_all_kernel(const float* __restrict__ x,
                               const float* __restrict__ Wq,
                               const float* __restrict__ Wk,
                               const float* __restrict__ Wv,
                               const float* __restrict__ Wp,
                               uint32_t* __restrict__ xt,
                               uint32_t* __restrict__ wt)
{
    size_t i = (size_t)blockIdx.x * blockDim.x + threadIdx.x;
    if (i >= TOTN4) return;
    const float* src;
    uint32_t* dst;
    if (i < XN4) {
        src = x + 4 * i;
        dst = xt + 4 * i;
    } else {
        size_t wi = i - XN4;
        int w = (int)(wi / WN4);
        size_t off = (wi % WN4) * 4;
        const float* ws[4] = {Wq, Wk, Wv, Wp};
        src = ws[w] + off;
        dst = wt + (size_t)w * WELEM + off;
    }
    float4 v = *(const float4*)src;
    *(uint4*)dst = make_uint4(f2tf32(v.x), f2tf32(v.y), f2tf32(v.z), f2tf32(v.w));
}

// ---------------------------------------------------------------------------
// tf32 tensor-core GEMM: C[M,768] = A[M,768] @ W[768,768]
// 128x128 CTA tile, BK=16, 128 threads (4 warps 2x2), warp tile 64x64.
// 3-stage cp.async pipeline, one __syncthreads per K-iter.
// ---------------------------------------------------------------------------
#define BM 128
#define BN 128
#define BK 16
#define NT (D / BK)      // 48
#define ASTR 20
#define BSTR 132
#define A_WORDS (BM * ASTR)               // 2560
#define STAGE_WORDS (A_WORDS + BK * BSTR) // 2560 + 2112 = 4672

template <int OUTMODE>
__device__ __forceinline__ void gemm_body(const uint32_t* __restrict__ A,
                                          const uint32_t* __restrict__ W,
                                          void* __restrict__ Cout,
                                          const float* __restrict__ bias)
{
    __shared__ uint32_t smem[3 * STAGE_WORDS];

    const int tid = threadIdx.x;
    const int lane = tid & 31;
    const int warp = tid >> 5;
    const int g  = lane >> 2;
    const int tg = lane & 3;
    const int mb = (warp >> 1) * 64;
    const int nb = (warp & 1) * 64;
    const int m0 = blockIdx.y * BM;
    const int n0 = blockIdx.x * BN;

    const uint32_t smBase = (uint32_t)__cvta_generic_to_shared(smem);

    auto load_tiles = [&](int kt, int buf) {
        const uint32_t aS = smBase + (uint32_t)(buf * STAGE_WORDS) * 4;
        const uint32_t bS = aS + A_WORDS * 4;
#pragma unroll
        for (int i = 0; i < 4; ++i) {
            int c = tid + (i << 7);
            int row = c >> 2;
            int co = (c & 3) << 2;
            cp16(aS + (uint32_t)(row * ASTR + co) * 4,
                 A + (size_t)(m0 + row) * D + kt * BK + co);
        }
#pragma unroll
        for (int i = 0; i < 4; ++i) {
            int c = tid + (i << 7);
            int row = c >> 5;
            int col = (c & 31) << 2;
            cp16(bS + (uint32_t)(row * BSTR + col) * 4,
                 W + (size_t)(kt * BK + row) * D + n0 + col);
        }
    };

    float acc[4][8][4] = {};

    load_tiles(0, 0); CP_COMMIT();
    load_tiles(1, 1); CP_COMMIT();

    for (int kt = 0; kt < NT; ++kt) {
        const int buf = kt % 3;
        if (kt + 1 < NT) { CP_WAIT(1); } else { CP_WAIT(0); }
        __syncthreads();
        if (kt + 2 < NT) {
            load_tiles(kt + 2, (kt + 2) % 3);
            CP_COMMIT();
        }

        const uint32_t* as = smem + buf * STAGE_WORDS;
        const uint32_t* bs = as + A_WORDS;
#pragma unroll
        for (int kk = 0; kk < BK; kk += 8) {
            uint32_t af[4][4];
#pragma unroll
            for (int i = 0; i < 4; ++i) {
                const int r = (mb + i * 16 + g) * ASTR + kk + tg;
                af[i][0] = as[r];
                af[i][1] = as[r + 8 * ASTR];
                af[i][2] = as[r + 4];
                af[i][3] = as[r + 8 * ASTR + 4];
            }
#pragma unroll
            for (int j = 0; j < 8; ++j) {
                const uint32_t b0 = bs[(kk + tg) * BSTR + nb + j * 8 + g];
                const uint32_t b1 = bs[(kk + tg + 4) * BSTR + nb + j * 8 + g];
#pragma unroll
                for (int i = 0; i < 4; ++i)
                    mma_tf32(acc[i][j], af[i][0], af[i][1], af[i][2], af[i][3], b0, b1);
            }
        }
    }

    // Epilogue (validated c-frag map)
#pragma unroll
    for (int j = 0; j < 8; ++j) {
        const int cn = n0 + nb + j * 8 + 2 * tg;
        float b0 = 0.f, b1 = 0.f;
        if (OUTMODE == 1) { b0 = bias[cn]; b1 = bias[cn + 1]; }
#pragma unroll
        for (int i = 0; i < 4; ++i) {
            const int rm = m0 + mb + i * 16 + g;
            if (OUTMODE == 0) {
                uint32_t* C = (uint32_t*)Cout;
                *(uint2*)(C + (size_t)rm * D + cn) =
                    make_uint2(f2tf32(acc[i][j][0]), f2tf32(acc[i][j][1]));
                *(uint2*)(C + (size_t)(rm + 8) * D + cn) =
                    make_uint2(f2tf32(acc[i][j][2]), f2tf32(acc[i][j][3]));
            } else {
                float* C = (float*)Cout;
                *(float2*)(C + (size_t)rm * D + cn) =
                    make_float2(acc[i][j][0] + b0, acc[i][j][1] + b1);
                *(float2*)(C + (size_t)(rm + 8) * D + cn) =
                    make_float2(acc[i][j][2] + b0, acc[i][j][3] + b1);
            }
        }
    }
}

__global__ void __launch_bounds__(128) qkv_kernel()
{
    const uint32_t* W = g_wt + (size_t)blockIdx.z * WELEM;
    uint32_t* C = (blockIdx.z == 0) ? g_qt : (blockIdx.z == 1) ? g_kt : g_vt;
    gemm_body<0>(g_xt, W, C, nullptr);
}

__global__ void __launch_bounds__(128) proj_kernel(const float* __restrict__ bias,
                                                   float* __restrict__ out)
{
    gemm_body<1>(g_att, g_wt + 3 * (size_t)WELEM, out, bias);
}

// ---------------------------------------------------------------------------
// tf32 flash attention, 128-query tile, 256 threads (8 warps x 16 rows).
// Separate P buffer -> no block syncs between S, softmax, PV (only syncwarp).
// q-tile 0 = queries [0,128) (nk=128); tiles 1..4 = [128,528) (nk=528).
// ---------------------------------------------------------------------------
#define QSTR 132
#define KSTR 68
#define PSTR 68
#define SM_QT 0
#define SM_KS (64 * QSTR)
#define SM_VS (SM_KS + 64 * KSTR)
#define SM_PS (SM_VS + 64 * KSTR)
#define SMEM_ATTN ((SM_PS + 128 * PSTR) * 4)   // 103424 B

__global__ void __launch_bounds__(256) attn_kernel()
{
    extern __shared__ uint32_t sm[];
    uint32_t* Qt = sm + SM_QT;   // [d][q]   64 x 128, stride 132
    uint32_t* Ks = sm + SM_KS;   // [d][key] 64 x 64,  stride 68
    uint32_t* Vs = sm + SM_VS;   // [key][d] 64 x 64,  stride 68
    uint32_t* Ps = sm + SM_PS;   // [q][key] 128 x 64, stride 68

    const int h = blockIdx.y, b = blockIdx.z;
    const int q0 = blockIdx.x << 7;
    const int nq = min(128, LSEQ - q0);
    const int nk = (q0 == 0) ? 128 : LSEQ;
    const int tid = threadIdx.x;
    const int lane = tid & 31;
    const int warp = tid >> 5;      // 0..7
    const int g  = lane >> 2;
    const int tg = lane & 3;
    const int mrow = warp * 16;
    const size_t base = (size_t)b * LSEQ * D + (size_t)h * DH;

    // Load Q transposed: Qt[d][q]
#pragma unroll
    for (int it = 0; it < 8; ++it) {
        int idx = tid + (it << 8);
        int r = idx & 127;
        int c4 = (idx >> 7) << 2;
        uint4 v = make_uint4(0u, 0u, 0u, 0u);
        if (r < nq) v = *(const uint4*)(g_qt + base + (size_t)(q0 + r) * D + c4);
        Qt[(c4 + 0) * QSTR + r] = v.x;
        Qt[(c4 + 1) * QSTR + r] = v.y;
        Qt[(c4 + 2) * QSTR + r] = v.z;
        Qt[(c4 + 3) * QSTR + r] = v.w;
    }

    float o[8][4] = {};
    float row_max[2] = {-1e30f, -1e30f};
    float row_sum[2] = {0.f, 0.f};

    for (int kt0 = 0; kt0 < nk; kt0 += 64) {
        const int nkv = min(64, nk - kt0);
        __syncthreads();   // prev-iter PV reads of Vs done (and Qt stores, iter 0)

        // Load K transposed + V row-major (zero-padded)
#pragma unroll
        for (int it = 0; it < 4; ++it) {
            int idx = tid + (it << 8);
            int r = idx & 63;
            int c4 = (idx >> 6) << 2;
            uint4 kv = make_uint4(0u, 0u, 0u, 0u);
            if (r < nkv) kv = *(const uint4*)(g_kt + base + (size_t)(kt0 + r) * D + c4);
            Ks[(c4 + 0) * KSTR + r] = kv.x;
            Ks[(c4 + 1) * KSTR + r] = kv.y;
            Ks[(c4 + 2) * KSTR + r] = kv.z;
            Ks[(c4 + 3) * KSTR + r] = kv.w;
            int r2 = idx >> 4;
            int c2 = (idx & 15) << 2;
            uint4 vv = make_uint4(0u, 0u, 0u, 0u);
            if (r2 < nkv) vv = *(const uint4*)(g_vt + base + (size_t)(kt0 + r2) * D + c2);
            *(uint4*)&Vs[r2 * KSTR + c2] = vv;
        }
        __syncthreads();

        // S = Q K^T : warp rows [mrow, mrow+16) x 64 keys
        float s[8][4] = {};
#pragma unroll
        for (int kk = 0; kk < 64; kk += 8) {
            uint32_t a0 = Qt[(kk + tg) * QSTR + mrow + g];
            uint32_t a1 = Qt[(kk + tg) * QSTR + mrow + g + 8];
            uint32_t a2 = Qt[(kk + tg + 4) * QSTR + mrow + g];
            uint32_t a3 = Qt[(kk + tg + 4) * QSTR + mrow + g + 8];
#pragma unroll
            for (int j = 0; j < 8; ++j) {
                uint32_t b0 = Ks[(kk + tg) * KSTR + j * 8 + g];
                uint32_t b1 = Ks[(kk + tg + 4) * KSTR + j * 8 + g];
                mma_tf32(s[j], a0, a1, a2, a3, b0, b1);
            }
        }

        // scale + mask
#pragma unroll
        for (int j = 0; j < 8; ++j) {
            const int col = kt0 + j * 8 + 2 * tg;
#pragma unroll
            for (int c = 0; c < 4; ++c) {
                float sv = s[j][c] * SCALE;
                if (col + (c & 1) >= nk) sv = -1e30f;
                s[j][c] = sv;
            }
        }

        // warp-local online softmax
        float m0v = -1e30f, m1v = -1e30f;
#pragma unroll
        for (int j = 0; j < 8; ++j) {
            m0v = fmaxf(m0v, fmaxf(s[j][0], s[j][1]));
            m1v = fmaxf(m1v, fmaxf(s[j][2], s[j][3]));
        }
        m0v = fmaxf(m0v, __shfl_xor_sync(0xffffffffu, m0v, 1));
        m0v = fmaxf(m0v, __shfl_xor_sync(0xffffffffu, m0v, 2));
        m1v = fmaxf(m1v, __shfl_xor_sync(0xffffffffu, m1v, 1));
        m1v = fmaxf(m1v, __shfl_xor_sync(0xffffffffu, m1v, 2));

        float nm0 = fmaxf(row_max[0], m0v);
        float nm1 = fmaxf(row_max[1], m1v);
        float corr0 = __expf(row_max[0] - nm0);
        float corr1 = __expf(row_max[1] - nm1);
        row_max[0] = nm0; row_max[1] = nm1;
        row_sum[0] *= corr0; row_sum[1] *= corr1;
#pragma unroll
        for (int j = 0; j < 8; ++j) {
            o[j][0] *= corr0; o[j][1] *= corr0;
            o[j][2] *= corr1; o[j][3] *= corr1;
        }

        float ps0 = 0.f, ps1 = 0.f;
#pragma unroll
        for (int j = 0; j < 8; ++j) {
            const int col = j * 8 + 2 * tg;
            float p0 = __expf(s[j][0] - nm0);
            float p1 = __expf(s[j][1] - nm0);
            float p2 = __expf(s[j][2] - nm1);
            float p3 = __expf(s[j][3] - nm1);
            ps0 += p0 + p1; ps1 += p2 + p3;
            Ps[(mrow + g) * PSTR + col]         = f2tf32(p0);
            Ps[(mrow + g) * PSTR + col + 1]     = f2tf32(p1);
            Ps[(mrow + g + 8) * PSTR + col]     = f2tf32(p2);
            Ps[(mrow + g + 8) * PSTR + col + 1] = f2tf32(p3);
        }
        ps0 += __shfl_xor_sync(0xffffffffu, ps0, 1);
        ps0 += __shfl_xor_sync(0xffffffffu, ps0, 2);
        ps1 += __shfl_xor_sync(0xffffffffu, ps1, 1);
        ps1 += __shfl_xor_sync(0xffffffffu, ps1, 2);
        row_sum[0] += ps0; row_sum[1] += ps1;
        __syncwarp();   // this warp's P rows fully visible to this warp

        // O += P @ V (warp reads only its own P rows)
#pragma unroll
        for (int kk = 0; kk < 64; kk += 8) {
            uint32_t a0 = Ps[(mrow + g) * PSTR + kk + tg];
            uint32_t a1 = Ps[(mrow + g + 8) * PSTR + kk + tg];
            uint32_t a2 = Ps[(mrow + g) * PSTR + kk + tg + 4];
            uint32_t a3 = Ps[(mrow + g + 8) * PSTR + kk + tg + 4];
#pragma unroll
            for (int j = 0; j < 8; ++j) {
                uint32_t b0 = Vs[(kk + tg) * KSTR + j * 8 + g];
                uint32_t b1 = Vs[(kk + tg + 4) * KSTR + j * 8 + g];
                mma_tf32(o[j], a0, a1, a2, a3, b0, b1);
            }
        }
    }

    const int r0 = mrow + g, r1 = r0 + 8;
    const float inv0 = 1.f / row_sum[0];
    const float inv1 = 1.f / row_sum[1];
#pragma unroll
    for (int j = 0; j < 8; ++j) {
        const int cn = j * 8 + 2 * tg;
        if (r0 < nq)
            *(uint2*)(g_att + base + (size_t)(q0 + r0) * D + cn) =
                make_uint2(f2tf32(o[j][0] * inv0), f2tf32(o[j][1] * inv0));
        if (r1 < nq)
            *(uint2*)(g_att + base + (size_t)(q0 + r1) * D + cn) =
                make_uint2(f2tf32(o[j][2] * inv1), f2tf32(o[j][3] * inv1));
    }
}

// ---------------------------------------------------------------------------
extern "C" void kernel_launch(void* const* d_in, const int* in_sizes, int n_in,
                              void* d_out, int out_size)
{
    const float* x   = (const float*)d_in[0];
    const float* Wq  = (const float*)d_in[1];
    const float* Wk  = (const float*)d_in[2];
    const float* Wv  = (const float*)d_in[3];
    const float* Wp  = (const float*)d_in[4];
    const float* bp  = (const float*)d_in[5];
    float* out = (float*)d_out;

    cudaFuncSetAttribute(attn_kernel,
                         cudaFuncAttributeMaxDynamicSharedMemorySize, SMEM_ATTN);

    uint32_t* g_xt_p;  cudaGetSymbolAddress((void**)&g_xt_p, g_xt);
    uint32_t* g_wt_p;  cudaGetSymbolAddress((void**)&g_wt_p, g_wt);

    const int cvt_blocks = (int)((TOTN4 + 255) / 256);
    cvt_all_kernel<<<cvt_blocks, 256>>>(x, Wq, Wk, Wv, Wp, g_xt_p, g_wt_p);

    dim3 gq(D / BN, MTOT / BM, 3);           // (6, 264, 3)
    qkv_kernel<<<gq, 128>>>();

    dim3 ga((LSEQ + 127) / 128, NHEADS, BSZ); // (5, 12, 64)
    attn_kernel<<<ga, 256, SMEM_ATTN>>>();

    dim3 gp(D / BN, MTOT / BM, 1);           // (6, 264)
    proj_kernel<<<gp, 128>>>(bp, out);
}